// round 5
// baseline (speedup 1.0000x reference)
#include <cuda_runtime.h>

#define NN 50000
#define EE 800000
#define DD 128
#define NV4 32          // DD/4
#define LN_EPS 1e-5f

// ---------------- device scratch (static globals; no allocation) -------------
static __device__ int    g_cnt_in[NN];
static __device__ int    g_cnt_out[NN];
static __device__ int    g_row_ptr[NN + 1];
static __device__ int    g_cursor[NN];
static __device__ int    g_col[EE];
static __device__ int    g_blk[128];
static __device__ float  g_iso[NN];
static __device__ float  g_isi[NN];
static __device__ float4 g_h1[NN * NV4];

__device__ __forceinline__ int clamp_idx(int v, int n) {
    unsigned u = (unsigned)v;
    return (u < (unsigned)n) ? v : 0;
}

// packed f32x2 helpers (FFMA2 — only reachable via PTX fma.rn.f32x2)
__device__ __forceinline__ unsigned long long pk2(float lo, float hi) {
    unsigned long long r;
    asm("mov.b64 %0, {%1, %2};" : "=l"(r) : "f"(lo), "f"(hi));
    return r;
}
__device__ __forceinline__ void upk2(float& lo, float& hi, unsigned long long v) {
    asm("mov.b64 {%0, %1}, %2;" : "=f"(lo), "=f"(hi) : "l"(v));
}
__device__ __forceinline__ void ffma2(unsigned long long& d,
                                      unsigned long long a, unsigned long long b) {
    asm("fma.rn.f32x2 %0, %1, %2, %0;" : "+l"(d) : "l"(a), "l"(b));
}

// ---------------- graph prep -------------------------------------------------
__global__ void k_zero(int n) {
    int i = blockIdx.x * blockDim.x + threadIdx.x;
    if (i < n) { g_cnt_in[i] = 0; g_cnt_out[i] = 0; g_cursor[i] = 0; }
}

__global__ void k_degree(const int* __restrict__ src,
                         const int* __restrict__ dst, int e, int n) {
    int i = blockIdx.x * blockDim.x + threadIdx.x;
    if (i < e) {
        atomicAdd(&g_cnt_out[clamp_idx(src[i], n)], 1);
        atomicAdd(&g_cnt_in [clamp_idx(dst[i], n)], 1);
    }
}

__global__ void k_scan1(int n) {
    __shared__ int sh[1024];
    int t = threadIdx.x;
    int i = blockIdx.x * 1024 + t;
    int v = (i < n) ? g_cnt_in[i] : 0;
    sh[t] = v;
    __syncthreads();
    #pragma unroll
    for (int off = 1; off < 1024; off <<= 1) {
        int x = (t >= off) ? sh[t - off] : 0;
        __syncthreads();
        sh[t] += x;
        __syncthreads();
    }
    int incl = sh[t];
    if (i < n) g_row_ptr[i] = incl - v;          // block-local exclusive
    if (t == 1023) g_blk[blockIdx.x] = incl;     // block total
}

// parallel scan of up to 64 block totals with one warp
__global__ void k_scan2(int nb, int n) {
    int lane = threadIdx.x;
    int b0 = lane, b1 = 32 + lane;
    int v0 = (b0 < nb) ? g_blk[b0] : 0;
    int v1 = (b1 < nb) ? g_blk[b1] : 0;
    int s0 = v0, s1 = v1;
    #pragma unroll
    for (int off = 1; off < 32; off <<= 1) {
        int t0 = __shfl_up_sync(0xffffffffu, s0, off);
        int t1 = __shfl_up_sync(0xffffffffu, s1, off);
        if (lane >= off) { s0 += t0; s1 += t1; }
    }
    int tot0 = __shfl_sync(0xffffffffu, s0, 31);
    s1 += tot0;
    int tot = __shfl_sync(0xffffffffu, s1, 31);
    if (b0 < nb) g_blk[b0] = s0 - v0;
    if (b1 < nb) g_blk[b1] = s1 - v1;
    if (lane == 0) g_row_ptr[n] = tot;
}

// add block offsets + compute degree norms (fused)
__global__ void k_scan3(int n) {
    int i = blockIdx.x * blockDim.x + threadIdx.x;
    if (i < n) {
        g_row_ptr[i] += g_blk[i >> 10];
        int co = g_cnt_out[i]; if (co < 1) co = 1;
        int ci = g_cnt_in[i];  if (ci < 1) ci = 1;
        g_iso[i] = rsqrtf((float)co);
        g_isi[i] = rsqrtf((float)ci);
    }
}

__global__ void k_scatter(const int* __restrict__ src,
                          const int* __restrict__ dst, int e, int n) {
    int i = blockIdx.x * blockDim.x + threadIdx.x;
    if (i < e) {
        int d = clamp_idx(dst[i], n);
        int pos = g_row_ptr[d] + atomicAdd(&g_cursor[d], 1);
        if (pos < EE) g_col[pos] = clamp_idx(src[i], n);
    }
}

// ---------------- fused layer: SpMM gather -> GEMM -> LN -> ReLU -------------
// Block = 4 warps (128 thr). Each warp owns 8 nodes:
//   phase 1: gather agg row per node (iso[src]-scaled via fmaf, isi post-scale),
//            store DUPLICATED (v,v) pairs to smem for FFMA2 consumption.
//   phase 2: 8-node register-blocked GEMM with packed fma.rn.f32x2.
//   phase 3: per-node warp LayerNorm + ReLU, store.
__global__ void __launch_bounds__(128) k_layer(
        const float4* __restrict__ in,
        const float*  __restrict__ Wp,
        const float*  __restrict__ bp,
        const float*  __restrict__ gp,
        const float*  __restrict__ bep,
        float4* __restrict__ out, int n) {
    // [warp][m][k2]: each 16B entry = {(v_k,v_k),(v_{k+1},v_{k+1})} -> 32 KB
    __shared__ ulonglong2 sdup[4][8][DD / 2];

    int t = threadIdx.x;
    int lane = t & 31;
    int w = t >> 5;
    int base = blockIdx.x * 32 + w * 8;

    // ---- phase 1: gather 8 rows ----
    #pragma unroll 1
    for (int m = 0; m < 8; m++) {
        int node = base + m;
        float4 acc = make_float4(0.f, 0.f, 0.f, 0.f);
        if (node < n) {
            int beg = g_row_ptr[node];
            int cnt = g_cnt_in[node];
            #pragma unroll 8
            for (int e = 0; e < cnt; e++) {
                int s = g_col[beg + e];
                float sc = g_iso[s];
                float4 v = in[s * NV4 + lane];
                acc.x = fmaf(v.x, sc, acc.x);
                acc.y = fmaf(v.y, sc, acc.y);
                acc.z = fmaf(v.z, sc, acc.z);
                acc.w = fmaf(v.w, sc, acc.w);
            }
            float si = g_isi[node];
            acc.x *= si; acc.y *= si; acc.z *= si; acc.w *= si;
        }
        // lane covers k = 4*lane .. 4*lane+3  ->  k2 = 2*lane, 2*lane+1
        ulonglong2 p0, p1;
        p0.x = pk2(acc.x, acc.x); p0.y = pk2(acc.y, acc.y);
        p1.x = pk2(acc.z, acc.z); p1.y = pk2(acc.w, acc.w);
        sdup[w][m][2 * lane]     = p0;
        sdup[w][m][2 * lane + 1] = p1;
    }
    __syncwarp();

    // ---- phase 2: GEMM, 8 nodes x 4 cols per thread, packed FFMA2 ----
    const float4* W4 = (const float4*)Wp;
    float4 bv = ((const float4*)bp)[lane];
    unsigned long long acc0[8], acc1[8];
    #pragma unroll
    for (int m = 0; m < 8; m++) {
        acc0[m] = pk2(bv.x, bv.y);
        acc1[m] = pk2(bv.z, bv.w);
    }

    #pragma unroll 4
    for (int k2 = 0; k2 < DD / 2; k2++) {
        float4 wa = W4[(2 * k2)     * NV4 + lane];
        float4 wb = W4[(2 * k2 + 1) * NV4 + lane];
        unsigned long long wa01 = pk2(wa.x, wa.y);
        unsigned long long wa23 = pk2(wa.z, wa.w);
        unsigned long long wb01 = pk2(wb.x, wb.y);
        unsigned long long wb23 = pk2(wb.z, wb.w);
        #pragma unroll
        for (int m = 0; m < 8; m++) {
            ulonglong2 s2 = sdup[w][m][k2];   // LDS.128 broadcast
            ffma2(acc0[m], s2.x, wa01);
            ffma2(acc1[m], s2.x, wa23);
            ffma2(acc0[m], s2.y, wb01);
            ffma2(acc1[m], s2.y, wb23);
        }
    }

    // ---- phase 3: LayerNorm + ReLU per node ----
    float4 gg = ((const float4*)gp)[lane];
    float4 bb = ((const float4*)bep)[lane];
    #pragma unroll 1
    for (int m = 0; m < 8; m++) {
        int node = base + m;
        float a0, a1, a2, a3;
        upk2(a0, a1, acc0[m]);
        upk2(a2, a3, acc1[m]);
        float sum = a0 + a1 + a2 + a3;
        float sq  = a0 * a0 + a1 * a1 + a2 * a2 + a3 * a3;
        #pragma unroll
        for (int off = 16; off > 0; off >>= 1) {
            sum += __shfl_xor_sync(0xffffffffu, sum, off);
            sq  += __shfl_xor_sync(0xffffffffu, sq,  off);
        }
        float mu  = sum * (1.0f / DD);
        float var = sq * (1.0f / DD) - mu * mu;
        float r   = rsqrtf(var + LN_EPS);
        float4 o4;
        o4.x = fmaxf(0.f, (a0 - mu) * r * gg.x + bb.x);
        o4.y = fmaxf(0.f, (a1 - mu) * r * gg.y + bb.y);
        o4.z = fmaxf(0.f, (a2 - mu) * r * gg.z + bb.z);
        o4.w = fmaxf(0.f, (a3 - mu) * r * gg.w + bb.w);
        if (node < n) out[node * NV4 + lane] = o4;
    }
}

// ---------------- host launch ------------------------------------------------
extern "C" void kernel_launch(void* const* d_in, const int* in_sizes, int n_in,
                              void* d_out, int out_size) {
    const float* feat = (const float*)d_in[0];
    const int*   src  = (const int*)d_in[1];   // JAX default: int64 request -> int32
    const int*   dst  = (const int*)d_in[2];
    const float* W1  = (const float*)d_in[3];
    const float* b1  = (const float*)d_in[4];
    const float* g1  = (const float*)d_in[5];
    const float* be1 = (const float*)d_in[6];
    const float* W2  = (const float*)d_in[7];
    const float* b2  = (const float*)d_in[8];
    const float* g2  = (const float*)d_in[9];
    const float* be2 = (const float*)d_in[10];

    int n = in_sizes[0] / DD;   // 50000
    int e = in_sizes[1];        // 800000

    int gbN  = (n + 255) / 256;
    int gbE  = (e + 255) / 256;
    int nbSc = (n + 1023) / 1024;
    int gbL  = (n + 31) / 32;   // 32 nodes per block (4 warps x 8 nodes)

    // graph prep
    k_zero   <<<gbN, 256>>>(n);
    k_degree <<<gbE, 256>>>(src, dst, e, n);
    k_scan1  <<<nbSc, 1024>>>(n);
    k_scan2  <<<1, 32>>>(nbSc, n);
    k_scan3  <<<gbN, 256>>>(n);
    k_scatter<<<gbE, 256>>>(src, dst, e, n);

    // fused layers
    k_layer<<<gbL, 128>>>((const float4*)feat, W1, b1, g1, be1, g_h1, n);
    k_layer<<<gbL, 128>>>(g_h1, W2, b2, g2, be2, (float4*)d_out, n);
}